// round 14
// baseline (speedup 1.0000x reference)
#include <cuda_runtime.h>
#include <cuda_fp16.h>
#include <cstdint>

// ---------------------------------------------------------------------------
// KANClassifier fp16 mma.sync. Round 14: GEMM1+GEMM2 fused into one kernel
// with per-mt completion counters so GEMM2 tiles execute inside GEMM1's
// 46%-occupied tail wave. Prep (round-12 winner) unchanged; GEMM mainloop
// byte-identical to the round-8 core (72.6% tensor).
// ---------------------------------------------------------------------------

#define BATCH   4096
#define IN_DIM  1024
#define KDIM    16384
#define HIDDEN  4096
#define CLASSES 1000
#define NPAD    1024

#define KT1 (KDIM / 32)               // 512
#define KT2 (HIDDEN / 32)             // 128
#define CONVB_BLOCKS (KT1 * (HIDDEN / 128))   // 16384
#define CONVH_BLOCKS (KT2 * (NPAD / 128))     // 1024
#define PREP_BLOCKS (2 * CONVB_BLOCKS + CONVH_BLOCKS)

#define G1_NT 32                      // GEMM1 n-tiles
#define G1_BLOCKS ((BATCH / 128) * G1_NT)   // 1024
#define G2_NT 8
#define G2_BLOCKS ((BATCH / 128) * G2_NT)   // 256
#define MT_COUNT (BATCH / 128)        // 32

__device__ __align__(1024) uint4 g_F  [(size_t)BATCH * KDIM / 8];
__device__ __align__(1024) uint4 g_PHI[(size_t)BATCH * HIDDEN / 8];
__device__ __align__(1024) uint4 g_WbP[(size_t)KDIM * HIDDEN / 8];
__device__ __align__(1024) uint4 g_WhP[(size_t)HIDDEN * NPAD / 8];
__device__ int g_done[MT_COUNT];

__device__ __forceinline__ uint32_t pack_half2(float a, float b) {
    __half2 h = __floats2half2_rn(a, b);
    return *reinterpret_cast<uint32_t*>(&h);
}
__device__ __forceinline__ float mufu_tanh(float v) {
    float r;
    asm("tanh.approx.f32 %0, %1;" : "=f"(r) : "f"(v));
    return r;
}
__device__ __forceinline__ void cp_async16(uint32_t saddr, const void* gptr) {
    asm volatile("cp.async.cg.shared.global [%0], [%1], 16;\n" :: "r"(saddr), "l"(gptr));
}

// ---------------------------------------------------------------------------
// Fused prep kernel (round-12 winner) + g_done zeroing.
// ---------------------------------------------------------------------------
__device__ __forceinline__ void feats_block(int blk,
                                            const float* __restrict__ x,
                                            const float* __restrict__ centers,
                                            const float* __restrict__ scales,
                                            uint4* __restrict__ F) {
    int cp = blk * 256 + threadIdx.x;
    int g2 = cp * 2;
    int lane = g2 & 31, grp = (g2 >> 5) & 7, ks = (g2 >> 8) & 1;
    int kt = (g2 >> 9) & (KT1 - 1), mt = g2 >> 18;
    int rlo = lane >> 2;
    int j0 = (lane & 3) * 2;
    int r = mt * 128 + grp * 16 + rlo;
    int d = kt * 2 + ks;

    float xv0 = __ldg(x + (size_t)r * IN_DIM + d);
    float xv1 = __ldg(x + (size_t)(r + 8) * IN_DIM + d);
    const float4* c4 = reinterpret_cast<const float4*>(centers + d * 16 + j0);
    const float4* s4 = reinterpret_cast<const float4*>(scales  + d * 16 + j0);
    float4 cA = __ldg(c4);
    float4 cB = __ldg(c4 + 2);
    float4 sA = __ldg(s4);
    float4 sB = __ldg(s4 + 2);

    uint4 o0, o1;
    o0.x = pack_half2(mufu_tanh((xv0 - cA.x) * sA.x), mufu_tanh((xv0 - cA.y) * sA.y));
    o0.y = pack_half2(mufu_tanh((xv1 - cA.x) * sA.x), mufu_tanh((xv1 - cA.y) * sA.y));
    o0.z = pack_half2(mufu_tanh((xv0 - cB.x) * sB.x), mufu_tanh((xv0 - cB.y) * sB.y));
    o0.w = pack_half2(mufu_tanh((xv1 - cB.x) * sB.x), mufu_tanh((xv1 - cB.y) * sB.y));
    o1.x = pack_half2(mufu_tanh((xv0 - cA.z) * sA.z), mufu_tanh((xv0 - cA.w) * sA.w));
    o1.y = pack_half2(mufu_tanh((xv1 - cA.z) * sA.z), mufu_tanh((xv1 - cA.w) * sA.w));
    o1.z = pack_half2(mufu_tanh((xv0 - cB.z) * sB.z), mufu_tanh((xv0 - cB.w) * sB.w));
    o1.w = pack_half2(mufu_tanh((xv1 - cB.z) * sB.z), mufu_tanh((xv1 - cB.w) * sB.w));
    F[g2]     = o0;
    F[g2 + 1] = o1;
}

__device__ __forceinline__ void convert_block(int tile, float (*s)[132],
                                              const float* __restrict__ W,
                                              uint4* __restrict__ out,
                                              int KT, int Nsrc) {
    const int kt = tile % KT, nt = tile / KT;
    const int tid = threadIdx.x;
    const int n0 = nt * 128;

    const float* wg = W + (size_t)(kt * 32) * Nsrc + n0;
#pragma unroll
    for (int p = 0; p < 4; p++) {
        int elem = p * 1024 + tid * 4;
        int row = elem >> 7, col = elem & 127;
        float4 v;
        if (n0 + col + 3 < Nsrc) {
            v = __ldg(reinterpret_cast<const float4*>(wg + (size_t)row * Nsrc + col));
        } else {
            v.x = (n0 + col     < Nsrc) ? __ldg(wg + (size_t)row * Nsrc + col)     : 0.f;
            v.y = (n0 + col + 1 < Nsrc) ? __ldg(wg + (size_t)row * Nsrc + col + 1) : 0.f;
            v.z = (n0 + col + 2 < Nsrc) ? __ldg(wg + (size_t)row * Nsrc + col + 2) : 0.f;
            v.w = (n0 + col + 3 < Nsrc) ? __ldg(wg + (size_t)row * Nsrc + col + 3) : 0.f;
        }
        s[row][col] = v.x; s[row][col + 1] = v.y;
        s[row][col + 2] = v.z; s[row][col + 3] = v.w;
    }
    __syncthreads();

#pragma unroll
    for (int q = 0; q < 2; q++) {
        int cc = tid * 2 + q;
        int lane = cc & 31, npair = (cc >> 5) & 7, ks = cc >> 8;
        int k0 = ks * 16 + (lane & 3) * 2;
        int c  = npair * 16 + (lane >> 2);
        uint4 o;
        o.x = pack_half2(s[k0][c],         s[k0 + 1][c]);
        o.y = pack_half2(s[k0 + 8][c],     s[k0 + 9][c]);
        o.z = pack_half2(s[k0][c + 8],     s[k0 + 1][c + 8]);
        o.w = pack_half2(s[k0 + 8][c + 8], s[k0 + 9][c + 8]);
        out[(size_t)tile * 512 + cc] = o;
    }
}

__global__ void prep_fused_kernel(const float* __restrict__ x,
                                  const float* __restrict__ centers,
                                  const float* __restrict__ scales,
                                  const float* __restrict__ Wb,
                                  const float* __restrict__ Wh,
                                  uint4* __restrict__ F,
                                  uint4* __restrict__ WbP,
                                  uint4* __restrict__ WhP) {
    __shared__ float s[32][132];
    int b = blockIdx.x;
    if (b == 0 && threadIdx.x < MT_COUNT) g_done[threadIdx.x] = 0;
    if (b < 2 * CONVB_BLOCKS) {
        if (b & 1) feats_block(b >> 1, x, centers, scales, F);
        else       convert_block(b >> 1, s, Wb, WbP, KT1, HIDDEN);
    } else {
        convert_block(b - 2 * CONVB_BLOCKS, s, Wh, WhP, KT2, CLASSES);
    }
}

// ---------------------------------------------------------------------------
// GEMM body (round-8 exact mainloop): 128x128 block, BK=64, 3 stages (96KB),
// 8 warps (2M x 4N), warp 64x32.
// ---------------------------------------------------------------------------
#define STAGES 3
#define A_CH 1024
#define B_CH 1024
#define SMEM_BYTES (STAGES * (A_CH + B_CH) * 16)   // 96KB

__device__ __forceinline__ void mma16816(float* d, const uint4& a,
                                         uint32_t b0, uint32_t b1) {
    asm volatile(
        "mma.sync.aligned.m16n8k16.row.col.f32.f16.f16.f32 "
        "{%0,%1,%2,%3}, {%4,%5,%6,%7}, {%8,%9}, {%0,%1,%2,%3};\n"
        : "+f"(d[0]), "+f"(d[1]), "+f"(d[2]), "+f"(d[3])
        : "r"(a.x), "r"(a.y), "r"(a.z), "r"(a.w), "r"(b0), "r"(b1));
}

template <bool SIGMOID, bool PACKED_OUT>
__device__ __forceinline__ void gemm_body(int mt, int nt,
                                          const uint4* __restrict__ Apk,
                                          const uint4* __restrict__ Bpk,
                                          const float* __restrict__ bias,
                                          void* __restrict__ outp,
                                          int KTs, int KTout, int Nreal) {
    extern __shared__ uint4 sm4[];
    uint4* As = sm4;
    uint4* Bs = sm4 + STAGES * A_CH;

    const int tid = threadIdx.x;
    const int lane = tid & 31;
    const int warp = tid >> 5;
    const int wm = warp & 1, wn = warp >> 1;
    const int lr = lane >> 2, lc = lane & 3;
    const int m0 = mt * 128, n0 = nt * 128;
    const int KT2c = KTs / 2;

    float acc[4][4][4];
#pragma unroll
    for (int i = 0; i < 4; i++)
#pragma unroll
        for (int j = 0; j < 4; j++)
#pragma unroll
            for (int k = 0; k < 4; k++) acc[i][j][k] = 0.f;

    auto load_stage = [&](int kt2, int s) {
        const uint4* ag = Apk + ((size_t)mt * KTs + kt2 * 2) * 512;
        uint4* as = As + s * A_CH;
#pragma unroll
        for (int p = 0; p < 4; p++) {
            int ci = tid + p * 256;
            cp_async16((uint32_t)__cvta_generic_to_shared(as + ci), ag + ci);
        }
        const uint4* bg = Bpk + ((size_t)nt * KTs + kt2 * 2) * 512;
        uint4* bs = Bs + s * B_CH;
#pragma unroll
        for (int p = 0; p < 4; p++) {
            int ci = tid + p * 256;
            cp_async16((uint32_t)__cvta_generic_to_shared(bs + ci), bg + ci);
        }
        asm volatile("cp.async.commit_group;\n");
    };

    load_stage(0, 0);
    load_stage(1, 1);

    int s = 0;
    for (int kt2 = 0; kt2 < KT2c; kt2++) {
        asm volatile("cp.async.wait_group 1;\n");
        __syncthreads();
        if (kt2 + 2 < KT2c) {
            int ns = s + 2; if (ns >= STAGES) ns -= STAGES;
            load_stage(kt2 + 2, ns);
        } else {
            asm volatile("cp.async.commit_group;\n");
        }

        const uint4* as = As + s * A_CH;
        const uint4* bs = Bs + s * B_CH;

#pragma unroll
        for (int ksg = 0; ksg < 4; ksg++) {
            const int half = ksg >> 1, ks = ksg & 1;
            uint4 av[4];
#pragma unroll
            for (int mf = 0; mf < 4; mf++)
                av[mf] = as[half * 512 + ks * 256 + (wm * 4 + mf) * 32 + lane];
            uint4 bv[2];
#pragma unroll
            for (int np = 0; np < 2; np++)
                bv[np] = bs[half * 512 + (ks * 8 + wn * 2 + np) * 32 + lane];
#pragma unroll
            for (int mf = 0; mf < 4; mf++)
#pragma unroll
                for (int np = 0; np < 2; np++) {
                    mma16816(acc[mf][2 * np],     av[mf], bv[np].x, bv[np].y);
                    mma16816(acc[mf][2 * np + 1], av[mf], bv[np].z, bv[np].w);
                }
        }
        if (++s == STAGES) s = 0;
    }

    // epilogue
#pragma unroll
    for (int mf = 0; mf < 4; mf++) {
        const int r0 = m0 + wm * 64 + mf * 16 + lr;
        const int grp = wm * 4 + mf;
#pragma unroll
        for (int npi = 0; npi < 2; npi++) {
            const int nf = npi * 2;
            const int c = n0 + wn * 32 + nf * 8 + lc * 2;
            float b0 = 0.f, b1 = 0.f, b2 = 0.f, b3 = 0.f;
            if (!PACKED_OUT) {
                if (c < Nreal)     b0 = __ldg(bias + c);
                if (c + 1 < Nreal) b1 = __ldg(bias + c + 1);
                if (c + 8 < Nreal) b2 = __ldg(bias + c + 8);
                if (c + 9 < Nreal) b3 = __ldg(bias + c + 9);
            } else {
                b0 = __ldg(bias + c);     b1 = __ldg(bias + c + 1);
                b2 = __ldg(bias + c + 8); b3 = __ldg(bias + c + 9);
            }
            float v00 = acc[mf][nf][0] + b0,     v01 = acc[mf][nf][1] + b1;
            float v10 = acc[mf][nf][2] + b0,     v11 = acc[mf][nf][3] + b1;
            float v20 = acc[mf][nf + 1][0] + b2, v21 = acc[mf][nf + 1][1] + b3;
            float v30 = acc[mf][nf + 1][2] + b2, v31 = acc[mf][nf + 1][3] + b3;
            if (SIGMOID) {
                v00 = 1.f / (1.f + __expf(-v00)); v01 = 1.f / (1.f + __expf(-v01));
                v10 = 1.f / (1.f + __expf(-v10)); v11 = 1.f / (1.f + __expf(-v11));
                v20 = 1.f / (1.f + __expf(-v20)); v21 = 1.f / (1.f + __expf(-v21));
                v30 = 1.f / (1.f + __expf(-v30)); v31 = 1.f / (1.f + __expf(-v31));
            }
            if (PACKED_OUT) {
                int kt2o = c >> 5;
                int ks2 = npi;
                size_t chunk = ((size_t)mt * KTout + kt2o) * 512
                             + ks2 * 256 + grp * 32 + lane;
                uint4 o;
                o.x = pack_half2(v00, v01);
                o.y = pack_half2(v10, v11);
                o.z = pack_half2(v20, v21);
                o.w = pack_half2(v30, v31);
                reinterpret_cast<uint4*>(outp)[chunk] = o;
            } else {
                float* C = reinterpret_cast<float*>(outp);
                if (c < Nreal)     C[(size_t)r0 * Nreal + c] = v00;
                if (c + 1 < Nreal) C[(size_t)r0 * Nreal + c + 1] = v01;
                if (c < Nreal)     C[(size_t)(r0 + 8) * Nreal + c] = v10;
                if (c + 1 < Nreal) C[(size_t)(r0 + 8) * Nreal + c + 1] = v11;
                if (c + 8 < Nreal) C[(size_t)r0 * Nreal + c + 8] = v20;
                if (c + 9 < Nreal) C[(size_t)r0 * Nreal + c + 9] = v21;
                if (c + 8 < Nreal) C[(size_t)(r0 + 8) * Nreal + c + 8] = v30;
                if (c + 9 < Nreal) C[(size_t)(r0 + 8) * Nreal + c + 9] = v31;
            }
        }
    }
}

// ---------------------------------------------------------------------------
// Fused GEMM1+GEMM2 kernel. Blocks [0, G1_BLOCKS): GEMM1 tiles (signal
// g_done[mt] when stored). Blocks [G1_BLOCKS, +G2_BLOCKS): GEMM2 tiles (wait
// for g_done[mt]==32). Deadlock-free: G2_BLOCKS(256) < slots(296).
// ---------------------------------------------------------------------------
__global__ void __launch_bounds__(256, 2)
gemm_fused_kernel(const uint4* __restrict__ F,
                  const uint4* __restrict__ WbP,
                  const float* __restrict__ bb,
                  uint4* __restrict__ PHI,
                  const uint4* __restrict__ WhP,
                  const float* __restrict__ bh,
                  float* __restrict__ out) {
    const int GRP = 8;
    if (blockIdx.x < G1_BLOCKS) {
        int cid = blockIdx.x;
        int per = GRP * G1_NT;
        int mt = (cid / per) * GRP + (cid % per) % GRP;
        int nt = (cid % per) / GRP;
        gemm_body<true, true>(mt, nt, F, WbP, bb, PHI, KT1, KT2, HIDDEN);
        __syncthreads();
        if (threadIdx.x == 0) {
            __threadfence();
            atomicAdd(&g_done[mt], 1);
        }
    } else {
        int cid = blockIdx.x - G1_BLOCKS;
        int per = GRP * G2_NT;
        int mt = (cid / per) * GRP + (cid % per) % GRP;
        int nt = (cid % per) / GRP;
        if (threadIdx.x == 0) {
            while (__ldcg((const int*)&g_done[mt]) < G1_NT) __nanosleep(200);
        }
        __syncthreads();
        __threadfence();
        gemm_body<false, false>(mt, nt, PHI, WhP, bh, out, KT2, 0, CLASSES);
    }
}

// ---------------------------------------------------------------------------
// Launch
// ---------------------------------------------------------------------------
extern "C" void kernel_launch(void* const* d_in, const int* in_sizes, int n_in,
                              void* d_out, int out_size) {
    const float* x       = (const float*)d_in[0];
    const float* centers = (const float*)d_in[1];
    const float* scales  = (const float*)d_in[2];
    const float* Wb      = (const float*)d_in[3];
    const float* bb      = (const float*)d_in[4];
    const float* Wh      = (const float*)d_in[5];
    const float* bh      = (const float*)d_in[6];
    float* out = (float*)d_out;

    uint4 *F, *PHI, *WbP, *WhP;
    cudaGetSymbolAddress((void**)&F, g_F);
    cudaGetSymbolAddress((void**)&PHI, g_PHI);
    cudaGetSymbolAddress((void**)&WbP, g_WbP);
    cudaGetSymbolAddress((void**)&WhP, g_WhP);

    cudaFuncSetAttribute((const void*)gemm_fused_kernel,
                         cudaFuncAttributeMaxDynamicSharedMemorySize, SMEM_BYTES);

    // 1) fused prep: feats + Wb pack + Wh pack + g_done zeroing
    prep_fused_kernel<<<PREP_BLOCKS, 256>>>(x, centers, scales, Wb, Wh,
                                            F, WbP, WhP);

    // 2) fused GEMM1 (+sigmoid, packed out) and GEMM2 (overlapped tail)
    gemm_fused_kernel<<<G1_BLOCKS + G2_BLOCKS, 256, SMEM_BYTES>>>(
        F, WbP, bb, PHI, WhP, bh, out);
}

// round 15
// speedup vs baseline: 1.0047x; 1.0047x over previous
#include <cuda_runtime.h>
#include <cuda_fp16.h>
#include <cstdint>

// ---------------------------------------------------------------------------
// KANClassifier fp16 mma.sync. Round 15: GEMM1+GEMM2 fused with dependency-
// aware grid ordering — GEMM2 block-groups interleaved right after their
// producer GEMM1 groups so they fill scheduler gaps instead of forming a
// 5th wave. Counters per mt; deadlock-free by dispatch order.
// ---------------------------------------------------------------------------

#define BATCH   4096
#define IN_DIM  1024
#define KDIM    16384
#define HIDDEN  4096
#define CLASSES 1000
#define NPAD    1024

#define KT1 (KDIM / 32)               // 512
#define KT2 (HIDDEN / 32)             // 128
#define CONVB_BLOCKS (KT1 * (HIDDEN / 128))   // 16384
#define CONVH_BLOCKS (KT2 * (NPAD / 128))     // 1024
#define PREP_BLOCKS (2 * CONVB_BLOCKS + CONVH_BLOCKS)

#define G1_NT 32
#define G2_NT 8
#define MT_COUNT (BATCH / 128)        // 32
#define TOTAL_BLOCKS 1280             // 4x(256 G1) + 4x(64 G2)

__device__ __align__(1024) uint4 g_F  [(size_t)BATCH * KDIM / 8];
__device__ __align__(1024) uint4 g_PHI[(size_t)BATCH * HIDDEN / 8];
__device__ __align__(1024) uint4 g_WbP[(size_t)KDIM * HIDDEN / 8];
__device__ __align__(1024) uint4 g_WhP[(size_t)HIDDEN * NPAD / 8];
__device__ int g_done[MT_COUNT];

__device__ __forceinline__ uint32_t pack_half2(float a, float b) {
    __half2 h = __floats2half2_rn(a, b);
    return *reinterpret_cast<uint32_t*>(&h);
}
__device__ __forceinline__ float mufu_tanh(float v) {
    float r;
    asm("tanh.approx.f32 %0, %1;" : "=f"(r) : "f"(v));
    return r;
}
__device__ __forceinline__ void cp_async16(uint32_t saddr, const void* gptr) {
    asm volatile("cp.async.cg.shared.global [%0], [%1], 16;\n" :: "r"(saddr), "l"(gptr));
}

// ---------------------------------------------------------------------------
// Fused prep kernel (round-12 winner) + g_done zeroing.
// ---------------------------------------------------------------------------
__device__ __forceinline__ void feats_block(int blk,
                                            const float* __restrict__ x,
                                            const float* __restrict__ centers,
                                            const float* __restrict__ scales,
                                            uint4* __restrict__ F) {
    int cp = blk * 256 + threadIdx.x;
    int g2 = cp * 2;
    int lane = g2 & 31, grp = (g2 >> 5) & 7, ks = (g2 >> 8) & 1;
    int kt = (g2 >> 9) & (KT1 - 1), mt = g2 >> 18;
    int rlo = lane >> 2;
    int j0 = (lane & 3) * 2;
    int r = mt * 128 + grp * 16 + rlo;
    int d = kt * 2 + ks;

    float xv0 = __ldg(x + (size_t)r * IN_DIM + d);
    float xv1 = __ldg(x + (size_t)(r + 8) * IN_DIM + d);
    const float4* c4 = reinterpret_cast<const float4*>(centers + d * 16 + j0);
    const float4* s4 = reinterpret_cast<const float4*>(scales  + d * 16 + j0);
    float4 cA = __ldg(c4);
    float4 cB = __ldg(c4 + 2);
    float4 sA = __ldg(s4);
    float4 sB = __ldg(s4 + 2);

    uint4 o0, o1;
    o0.x = pack_half2(mufu_tanh((xv0 - cA.x) * sA.x), mufu_tanh((xv0 - cA.y) * sA.y));
    o0.y = pack_half2(mufu_tanh((xv1 - cA.x) * sA.x), mufu_tanh((xv1 - cA.y) * sA.y));
    o0.z = pack_half2(mufu_tanh((xv0 - cB.x) * sB.x), mufu_tanh((xv0 - cB.y) * sB.y));
    o0.w = pack_half2(mufu_tanh((xv1 - cB.x) * sB.x), mufu_tanh((xv1 - cB.y) * sB.y));
    o1.x = pack_half2(mufu_tanh((xv0 - cA.z) * sA.z), mufu_tanh((xv0 - cA.w) * sA.w));
    o1.y = pack_half2(mufu_tanh((xv1 - cA.z) * sA.z), mufu_tanh((xv1 - cA.w) * sA.w));
    o1.z = pack_half2(mufu_tanh((xv0 - cB.z) * sB.z), mufu_tanh((xv0 - cB.w) * sB.w));
    o1.w = pack_half2(mufu_tanh((xv1 - cB.z) * sB.z), mufu_tanh((xv1 - cB.w) * sB.w));
    F[g2]     = o0;
    F[g2 + 1] = o1;
}

__device__ __forceinline__ void convert_block(int tile, float (*s)[132],
                                              const float* __restrict__ W,
                                              uint4* __restrict__ out,
                                              int KT, int Nsrc) {
    const int kt = tile % KT, nt = tile / KT;
    const int tid = threadIdx.x;
    const int n0 = nt * 128;

    const float* wg = W + (size_t)(kt * 32) * Nsrc + n0;
#pragma unroll
    for (int p = 0; p < 4; p++) {
        int elem = p * 1024 + tid * 4;
        int row = elem >> 7, col = elem & 127;
        float4 v;
        if (n0 + col + 3 < Nsrc) {
            v = __ldg(reinterpret_cast<const float4*>(wg + (size_t)row * Nsrc + col));
        } else {
            v.x = (n0 + col     < Nsrc) ? __ldg(wg + (size_t)row * Nsrc + col)     : 0.f;
            v.y = (n0 + col + 1 < Nsrc) ? __ldg(wg + (size_t)row * Nsrc + col + 1) : 0.f;
            v.z = (n0 + col + 2 < Nsrc) ? __ldg(wg + (size_t)row * Nsrc + col + 2) : 0.f;
            v.w = (n0 + col + 3 < Nsrc) ? __ldg(wg + (size_t)row * Nsrc + col + 3) : 0.f;
        }
        s[row][col] = v.x; s[row][col + 1] = v.y;
        s[row][col + 2] = v.z; s[row][col + 3] = v.w;
    }
    __syncthreads();

#pragma unroll
    for (int q = 0; q < 2; q++) {
        int cc = tid * 2 + q;
        int lane = cc & 31, npair = (cc >> 5) & 7, ks = cc >> 8;
        int k0 = ks * 16 + (lane & 3) * 2;
        int c  = npair * 16 + (lane >> 2);
        uint4 o;
        o.x = pack_half2(s[k0][c],         s[k0 + 1][c]);
        o.y = pack_half2(s[k0 + 8][c],     s[k0 + 9][c]);
        o.z = pack_half2(s[k0][c + 8],     s[k0 + 1][c + 8]);
        o.w = pack_half2(s[k0 + 8][c + 8], s[k0 + 9][c + 8]);
        out[(size_t)tile * 512 + cc] = o;
    }
}

__global__ void prep_fused_kernel(const float* __restrict__ x,
                                  const float* __restrict__ centers,
                                  const float* __restrict__ scales,
                                  const float* __restrict__ Wb,
                                  const float* __restrict__ Wh,
                                  uint4* __restrict__ F,
                                  uint4* __restrict__ WbP,
                                  uint4* __restrict__ WhP) {
    __shared__ float s[32][132];
    int b = blockIdx.x;
    if (b == 0 && threadIdx.x < MT_COUNT) g_done[threadIdx.x] = 0;
    if (b < 2 * CONVB_BLOCKS) {
        if (b & 1) feats_block(b >> 1, x, centers, scales, F);
        else       convert_block(b >> 1, s, Wb, WbP, KT1, HIDDEN);
    } else {
        convert_block(b - 2 * CONVB_BLOCKS, s, Wh, WhP, KT2, CLASSES);
    }
}

// ---------------------------------------------------------------------------
// GEMM body (round-8 exact mainloop): 128x128 block, BK=64, 3 stages (96KB),
// 8 warps (2M x 4N), warp 64x32.
// ---------------------------------------------------------------------------
#define STAGES 3
#define A_CH 1024
#define B_CH 1024
#define SMEM_BYTES (STAGES * (A_CH + B_CH) * 16)   // 96KB

__device__ __forceinline__ void mma16816(float* d, const uint4& a,
                                         uint32_t b0, uint32_t b1) {
    asm volatile(
        "mma.sync.aligned.m16n8k16.row.col.f32.f16.f16.f32 "
        "{%0,%1,%2,%3}, {%4,%5,%6,%7}, {%8,%9}, {%0,%1,%2,%3};\n"
        : "+f"(d[0]), "+f"(d[1]), "+f"(d[2]), "+f"(d[3])
        : "r"(a.x), "r"(a.y), "r"(a.z), "r"(a.w), "r"(b0), "r"(b1));
}

template <bool SIGMOID, bool PACKED_OUT>
__device__ __forceinline__ void gemm_body(int mt, int nt,
                                          const uint4* __restrict__ Apk,
                                          const uint4* __restrict__ Bpk,
                                          const float* __restrict__ bias,
                                          void* __restrict__ outp,
                                          int KTs, int KTout, int Nreal) {
    extern __shared__ uint4 sm4[];
    uint4* As = sm4;
    uint4* Bs = sm4 + STAGES * A_CH;

    const int tid = threadIdx.x;
    const int lane = tid & 31;
    const int warp = tid >> 5;
    const int wm = warp & 1, wn = warp >> 1;
    const int lr = lane >> 2, lc = lane & 3;
    const int m0 = mt * 128, n0 = nt * 128;
    const int KT2c = KTs / 2;

    float acc[4][4][4];
#pragma unroll
    for (int i = 0; i < 4; i++)
#pragma unroll
        for (int j = 0; j < 4; j++)
#pragma unroll
            for (int k = 0; k < 4; k++) acc[i][j][k] = 0.f;

    auto load_stage = [&](int kt2, int s) {
        const uint4* ag = Apk + ((size_t)mt * KTs + kt2 * 2) * 512;
        uint4* as = As + s * A_CH;
#pragma unroll
        for (int p = 0; p < 4; p++) {
            int ci = tid + p * 256;
            cp_async16((uint32_t)__cvta_generic_to_shared(as + ci), ag + ci);
        }
        const uint4* bg = Bpk + ((size_t)nt * KTs + kt2 * 2) * 512;
        uint4* bs = Bs + s * B_CH;
#pragma unroll
        for (int p = 0; p < 4; p++) {
            int ci = tid + p * 256;
            cp_async16((uint32_t)__cvta_generic_to_shared(bs + ci), bg + ci);
        }
        asm volatile("cp.async.commit_group;\n");
    };

    load_stage(0, 0);
    load_stage(1, 1);

    int s = 0;
    for (int kt2 = 0; kt2 < KT2c; kt2++) {
        asm volatile("cp.async.wait_group 1;\n");
        __syncthreads();
        if (kt2 + 2 < KT2c) {
            int ns = s + 2; if (ns >= STAGES) ns -= STAGES;
            load_stage(kt2 + 2, ns);
        } else {
            asm volatile("cp.async.commit_group;\n");
        }

        const uint4* as = As + s * A_CH;
        const uint4* bs = Bs + s * B_CH;

#pragma unroll
        for (int ksg = 0; ksg < 4; ksg++) {
            const int half = ksg >> 1, ks = ksg & 1;
            uint4 av[4];
#pragma unroll
            for (int mf = 0; mf < 4; mf++)
                av[mf] = as[half * 512 + ks * 256 + (wm * 4 + mf) * 32 + lane];
            uint4 bv[2];
#pragma unroll
            for (int np = 0; np < 2; np++)
                bv[np] = bs[half * 512 + (ks * 8 + wn * 2 + np) * 32 + lane];
#pragma unroll
            for (int mf = 0; mf < 4; mf++)
#pragma unroll
                for (int np = 0; np < 2; np++) {
                    mma16816(acc[mf][2 * np],     av[mf], bv[np].x, bv[np].y);
                    mma16816(acc[mf][2 * np + 1], av[mf], bv[np].z, bv[np].w);
                }
        }
        if (++s == STAGES) s = 0;
    }

    // epilogue
#pragma unroll
    for (int mf = 0; mf < 4; mf++) {
        const int r0 = m0 + wm * 64 + mf * 16 + lr;
        const int grp = wm * 4 + mf;
#pragma unroll
        for (int npi = 0; npi < 2; npi++) {
            const int nf = npi * 2;
            const int c = n0 + wn * 32 + nf * 8 + lc * 2;
            float b0 = 0.f, b1 = 0.f, b2 = 0.f, b3 = 0.f;
            if (!PACKED_OUT) {
                if (c < Nreal)     b0 = __ldg(bias + c);
                if (c + 1 < Nreal) b1 = __ldg(bias + c + 1);
                if (c + 8 < Nreal) b2 = __ldg(bias + c + 8);
                if (c + 9 < Nreal) b3 = __ldg(bias + c + 9);
            } else {
                b0 = __ldg(bias + c);     b1 = __ldg(bias + c + 1);
                b2 = __ldg(bias + c + 8); b3 = __ldg(bias + c + 9);
            }
            float v00 = acc[mf][nf][0] + b0,     v01 = acc[mf][nf][1] + b1;
            float v10 = acc[mf][nf][2] + b0,     v11 = acc[mf][nf][3] + b1;
            float v20 = acc[mf][nf + 1][0] + b2, v21 = acc[mf][nf + 1][1] + b3;
            float v30 = acc[mf][nf + 1][2] + b2, v31 = acc[mf][nf + 1][3] + b3;
            if (SIGMOID) {
                v00 = 1.f / (1.f + __expf(-v00)); v01 = 1.f / (1.f + __expf(-v01));
                v10 = 1.f / (1.f + __expf(-v10)); v11 = 1.f / (1.f + __expf(-v11));
                v20 = 1.f / (1.f + __expf(-v20)); v21 = 1.f / (1.f + __expf(-v21));
                v30 = 1.f / (1.f + __expf(-v30)); v31 = 1.f / (1.f + __expf(-v31));
            }
            if (PACKED_OUT) {
                int kt2o = c >> 5;
                int ks2 = npi;
                size_t chunk = ((size_t)mt * KTout + kt2o) * 512
                             + ks2 * 256 + grp * 32 + lane;
                uint4 o;
                o.x = pack_half2(v00, v01);
                o.y = pack_half2(v10, v11);
                o.z = pack_half2(v20, v21);
                o.w = pack_half2(v30, v31);
                reinterpret_cast<uint4*>(outp)[chunk] = o;
            } else {
                float* C = reinterpret_cast<float*>(outp);
                if (c < Nreal)     C[(size_t)r0 * Nreal + c] = v00;
                if (c + 1 < Nreal) C[(size_t)r0 * Nreal + c + 1] = v01;
                if (c < Nreal)     C[(size_t)(r0 + 8) * Nreal + c] = v10;
                if (c + 1 < Nreal) C[(size_t)(r0 + 8) * Nreal + c + 1] = v11;
                if (c + 8 < Nreal) C[(size_t)r0 * Nreal + c + 8] = v20;
                if (c + 9 < Nreal) C[(size_t)r0 * Nreal + c + 9] = v21;
                if (c + 8 < Nreal) C[(size_t)(r0 + 8) * Nreal + c + 8] = v30;
                if (c + 9 < Nreal) C[(size_t)(r0 + 8) * Nreal + c + 9] = v31;
            }
        }
    }
}

// ---------------------------------------------------------------------------
// Fused GEMM kernel with dependency-aware ordering.
// Segments: [G1 g0 |G1 g1 |G2 g0 |G1 g2 |G2 g1 |G1 g3 |G2 g2 |G2 g3]
//            0-255  256-511 512-575 576-831 832-895 896-1151 1152-1215 1216-1279
// Within a segment: mt = group*8 + (local & 7), nt = local >> 3.
// ---------------------------------------------------------------------------
__global__ void __launch_bounds__(256, 2)
gemm_fused_kernel(const uint4* __restrict__ F,
                  const uint4* __restrict__ WbP,
                  const float* __restrict__ bb,
                  uint4* __restrict__ PHI,
                  const uint4* __restrict__ WhP,
                  const float* __restrict__ bh,
                  float* __restrict__ out) {
    int b = blockIdx.x;
    int group, local;
    bool isG2;
    if      (b <  256) { group = 0; local = b;        isG2 = false; }
    else if (b <  512) { group = 1; local = b - 256;  isG2 = false; }
    else if (b <  576) { group = 0; local = b - 512;  isG2 = true;  }
    else if (b <  832) { group = 2; local = b - 576;  isG2 = false; }
    else if (b <  896) { group = 1; local = b - 832;  isG2 = true;  }
    else if (b < 1152) { group = 3; local = b - 896;  isG2 = false; }
    else if (b < 1216) { group = 2; local = b - 1152; isG2 = true;  }
    else               { group = 3; local = b - 1216; isG2 = true;  }

    int mt = group * 8 + (local & 7);
    int nt = local >> 3;

    if (!isG2) {
        gemm_body<true, true>(mt, nt, F, WbP, bb, PHI, KT1, KT2, HIDDEN);
        __syncthreads();
        if (threadIdx.x == 0) {
            __threadfence();
            atomicAdd(&g_done[mt], 1);
        }
    } else {
        if (threadIdx.x == 0) {
            while (__ldcg((const int*)&g_done[mt]) < G1_NT) __nanosleep(200);
        }
        __syncthreads();
        __threadfence();
        gemm_body<false, false>(mt, nt, PHI, WhP, bh, out, KT2, 0, CLASSES);
    }
}

// ---------------------------------------------------------------------------
// Launch
// ---------------------------------------------------------------------------
extern "C" void kernel_launch(void* const* d_in, const int* in_sizes, int n_in,
                              void* d_out, int out_size) {
    const float* x       = (const float*)d_in[0];
    const float* centers = (const float*)d_in[1];
    const float* scales  = (const float*)d_in[2];
    const float* Wb      = (const float*)d_in[3];
    const float* bb      = (const float*)d_in[4];
    const float* Wh      = (const float*)d_in[5];
    const float* bh      = (const float*)d_in[6];
    float* out = (float*)d_out;

    uint4 *F, *PHI, *WbP, *WhP;
    cudaGetSymbolAddress((void**)&F, g_F);
    cudaGetSymbolAddress((void**)&PHI, g_PHI);
    cudaGetSymbolAddress((void**)&WbP, g_WbP);
    cudaGetSymbolAddress((void**)&WhP, g_WhP);

    cudaFuncSetAttribute((const void*)gemm_fused_kernel,
                         cudaFuncAttributeMaxDynamicSharedMemorySize, SMEM_BYTES);

    // 1) fused prep: feats + Wb pack + Wh pack + g_done zeroing
    prep_fused_kernel<<<PREP_BLOCKS, 256>>>(x, centers, scales, Wb, Wh,
                                            F, WbP, WhP);

    // 2) fused GEMM1 (+sigmoid, packed out) and GEMM2 (dependency-ordered)
    gemm_fused_kernel<<<TOTAL_BLOCKS, 256, SMEM_BYTES>>>(
        F, WbP, bb, PHI, WhP, bh, out);
}

// round 16
// speedup vs baseline: 1.0467x; 1.0419x over previous
#include <cuda_runtime.h>
#include <cuda_fp16.h>
#include <cstdint>

// ---------------------------------------------------------------------------
// KANClassifier fp16 mma.sync. Round 16: round-12 structure (best, 1434.7us)
// + cp.async issuance spread across ksg steps (kills the per-iteration LSU
// burst colliding with fragment LDS) + unguarded GEMM2 epilogue fast path.
// ---------------------------------------------------------------------------

#define BATCH   4096
#define IN_DIM  1024
#define KDIM    16384
#define HIDDEN  4096
#define CLASSES 1000
#define NPAD    1024

#define KT1 (KDIM / 32)               // 512
#define KT2 (HIDDEN / 32)             // 128
#define CONVB_BLOCKS (KT1 * (HIDDEN / 128))   // 16384
#define CONVH_BLOCKS (KT2 * (NPAD / 128))     // 1024
#define PREP_BLOCKS (2 * CONVB_BLOCKS + CONVH_BLOCKS)

__device__ __align__(1024) uint4 g_F  [(size_t)BATCH * KDIM / 8];
__device__ __align__(1024) uint4 g_PHI[(size_t)BATCH * HIDDEN / 8];
__device__ __align__(1024) uint4 g_WbP[(size_t)KDIM * HIDDEN / 8];
__device__ __align__(1024) uint4 g_WhP[(size_t)HIDDEN * NPAD / 8];

__device__ __forceinline__ uint32_t pack_half2(float a, float b) {
    __half2 h = __floats2half2_rn(a, b);
    return *reinterpret_cast<uint32_t*>(&h);
}
__device__ __forceinline__ float mufu_tanh(float v) {
    float r;
    asm("tanh.approx.f32 %0, %1;" : "=f"(r) : "f"(v));
    return r;
}
__device__ __forceinline__ void cp_async16(uint32_t saddr, const void* gptr) {
    asm volatile("cp.async.cg.shared.global [%0], [%1], 16;\n" :: "r"(saddr), "l"(gptr));
}

// ---------------------------------------------------------------------------
// Fused prep kernel (round-12 winner, unchanged).
// ---------------------------------------------------------------------------
__device__ __forceinline__ void feats_block(int blk,
                                            const float* __restrict__ x,
                                            const float* __restrict__ centers,
                                            const float* __restrict__ scales,
                                            uint4* __restrict__ F) {
    int cp = blk * 256 + threadIdx.x;
    int g2 = cp * 2;
    int lane = g2 & 31, grp = (g2 >> 5) & 7, ks = (g2 >> 8) & 1;
    int kt = (g2 >> 9) & (KT1 - 1), mt = g2 >> 18;
    int rlo = lane >> 2;
    int j0 = (lane & 3) * 2;
    int r = mt * 128 + grp * 16 + rlo;
    int d = kt * 2 + ks;

    float xv0 = __ldg(x + (size_t)r * IN_DIM + d);
    float xv1 = __ldg(x + (size_t)(r + 8) * IN_DIM + d);
    const float4* c4 = reinterpret_cast<const float4*>(centers + d * 16 + j0);
    const float4* s4 = reinterpret_cast<const float4*>(scales  + d * 16 + j0);
    float4 cA = __ldg(c4);
    float4 cB = __ldg(c4 + 2);
    float4 sA = __ldg(s4);
    float4 sB = __ldg(s4 + 2);

    uint4 o0, o1;
    o0.x = pack_half2(mufu_tanh((xv0 - cA.x) * sA.x), mufu_tanh((xv0 - cA.y) * sA.y));
    o0.y = pack_half2(mufu_tanh((xv1 - cA.x) * sA.x), mufu_tanh((xv1 - cA.y) * sA.y));
    o0.z = pack_half2(mufu_tanh((xv0 - cB.x) * sB.x), mufu_tanh((xv0 - cB.y) * sB.y));
    o0.w = pack_half2(mufu_tanh((xv1 - cB.x) * sB.x), mufu_tanh((xv1 - cB.y) * sB.y));
    o1.x = pack_half2(mufu_tanh((xv0 - cA.z) * sA.z), mufu_tanh((xv0 - cA.w) * sA.w));
    o1.y = pack_half2(mufu_tanh((xv1 - cA.z) * sA.z), mufu_tanh((xv1 - cA.w) * sA.w));
    o1.z = pack_half2(mufu_tanh((xv0 - cB.z) * sB.z), mufu_tanh((xv0 - cB.w) * sB.w));
    o1.w = pack_half2(mufu_tanh((xv1 - cB.z) * sB.z), mufu_tanh((xv1 - cB.w) * sB.w));
    F[g2]     = o0;
    F[g2 + 1] = o1;
}

__device__ __forceinline__ void convert_block(int tile, float (*s)[132],
                                              const float* __restrict__ W,
                                              uint4* __restrict__ out,
                                              int KT, int Nsrc) {
    const int kt = tile % KT, nt = tile / KT;
    const int tid = threadIdx.x;
    const int n0 = nt * 128;

    const float* wg = W + (size_t)(kt * 32) * Nsrc + n0;
#pragma unroll
    for (int p = 0; p < 4; p++) {
        int elem = p * 1024 + tid * 4;
        int row = elem >> 7, col = elem & 127;
        float4 v;
        if (n0 + col + 3 < Nsrc) {
            v = __ldg(reinterpret_cast<const float4*>(wg + (size_t)row * Nsrc + col));
        } else {
            v.x = (n0 + col     < Nsrc) ? __ldg(wg + (size_t)row * Nsrc + col)     : 0.f;
            v.y = (n0 + col + 1 < Nsrc) ? __ldg(wg + (size_t)row * Nsrc + col + 1) : 0.f;
            v.z = (n0 + col + 2 < Nsrc) ? __ldg(wg + (size_t)row * Nsrc + col + 2) : 0.f;
            v.w = (n0 + col + 3 < Nsrc) ? __ldg(wg + (size_t)row * Nsrc + col + 3) : 0.f;
        }
        s[row][col] = v.x; s[row][col + 1] = v.y;
        s[row][col + 2] = v.z; s[row][col + 3] = v.w;
    }
    __syncthreads();

#pragma unroll
    for (int q = 0; q < 2; q++) {
        int cc = tid * 2 + q;
        int lane = cc & 31, npair = (cc >> 5) & 7, ks = cc >> 8;
        int k0 = ks * 16 + (lane & 3) * 2;
        int c  = npair * 16 + (lane >> 2);
        uint4 o;
        o.x = pack_half2(s[k0][c],         s[k0 + 1][c]);
        o.y = pack_half2(s[k0 + 8][c],     s[k0 + 9][c]);
        o.z = pack_half2(s[k0][c + 8],     s[k0 + 1][c + 8]);
        o.w = pack_half2(s[k0 + 8][c + 8], s[k0 + 9][c + 8]);
        out[(size_t)tile * 512 + cc] = o;
    }
}

__global__ void prep_fused_kernel(const float* __restrict__ x,
                                  const float* __restrict__ centers,
                                  const float* __restrict__ scales,
                                  const float* __restrict__ Wb,
                                  const float* __restrict__ Wh,
                                  uint4* __restrict__ F,
                                  uint4* __restrict__ WbP,
                                  uint4* __restrict__ WhP) {
    __shared__ float s[32][132];
    int b = blockIdx.x;
    if (b < 2 * CONVB_BLOCKS) {
        if (b & 1) feats_block(b >> 1, x, centers, scales, F);
        else       convert_block(b >> 1, s, Wb, WbP, KT1, HIDDEN);
    } else {
        convert_block(b - 2 * CONVB_BLOCKS, s, Wh, WhP, KT2, CLASSES);
    }
}

// ---------------------------------------------------------------------------
// fp16 GEMM: 128x128 block, BK=64, 3 stages (96KB), 8 warps (2M x 4N),
// warp 64x32, 2 CTAs/SM. cp.async spread 2-per-ksg (1 A + 1 B).
// ---------------------------------------------------------------------------
#define STAGES 3
#define A_CH 1024
#define B_CH 1024
#define SMEM_BYTES (STAGES * (A_CH + B_CH) * 16)   // 96KB

__device__ __forceinline__ void mma16816(float* d, const uint4& a,
                                         uint32_t b0, uint32_t b1) {
    asm volatile(
        "mma.sync.aligned.m16n8k16.row.col.f32.f16.f16.f32 "
        "{%0,%1,%2,%3}, {%4,%5,%6,%7}, {%8,%9}, {%0,%1,%2,%3};\n"
        : "+f"(d[0]), "+f"(d[1]), "+f"(d[2]), "+f"(d[3])
        : "r"(a.x), "r"(a.y), "r"(a.z), "r"(a.w), "r"(b0), "r"(b1));
}

template <bool SIGMOID, bool PACKED_OUT>
__global__ void __launch_bounds__(256, 2)
gemm_fp16_kernel(const uint4* __restrict__ Apk,
                 const uint4* __restrict__ Bpk,
                 const float* __restrict__ bias,
                 void* __restrict__ outp,
                 int KTs, int KTout, int Nreal, int nTiles) {
    extern __shared__ uint4 sm4[];
    uint4* As = sm4;
    uint4* Bs = sm4 + STAGES * A_CH;

    const int tid = threadIdx.x;
    const int lane = tid & 31;
    const int warp = tid >> 5;
    const int wm = warp & 1, wn = warp >> 1;
    const int lr = lane >> 2, lc = lane & 3;

    const int GRP = 8;
    int per = GRP * nTiles;
    int mt = (blockIdx.x / per) * GRP + (blockIdx.x % per) % GRP;
    int nt = (blockIdx.x % per) / GRP;
    const int m0 = mt * 128, n0 = nt * 128;
    const int KT2c = KTs / 2;

    float acc[4][4][4];
#pragma unroll
    for (int i = 0; i < 4; i++)
#pragma unroll
        for (int j = 0; j < 4; j++)
#pragma unroll
            for (int k = 0; k < 4; k++) acc[i][j][k] = 0.f;

    // issue one A chunk + one B chunk (p in 0..3) of stage s for k-tile kt2
    auto load_part = [&](int kt2, int s, int p) {
        int ci = tid + p * 256;
        const uint4* ag = Apk + ((size_t)mt * KTs + kt2 * 2) * 512;
        cp_async16((uint32_t)__cvta_generic_to_shared(As + s * A_CH + ci), ag + ci);
        const uint4* bg = Bpk + ((size_t)nt * KTs + kt2 * 2) * 512;
        cp_async16((uint32_t)__cvta_generic_to_shared(Bs + s * B_CH + ci), bg + ci);
    };
    auto load_full = [&](int kt2, int s) {
#pragma unroll
        for (int p = 0; p < 4; p++) load_part(kt2, s, p);
        asm volatile("cp.async.commit_group;\n");
    };

    load_full(0, 0);
    load_full(1, 1);

    int s = 0;
    for (int kt2 = 0; kt2 < KT2c; kt2++) {
        asm volatile("cp.async.wait_group 1;\n");
        __syncthreads();
        const bool pref = (kt2 + 2 < KT2c);
        int ns = s + 2; if (ns >= STAGES) ns -= STAGES;

        const uint4* as = As + s * A_CH;
        const uint4* bs = Bs + s * B_CH;

#pragma unroll
        for (int ksg = 0; ksg < 4; ksg++) {
            if (pref) load_part(kt2 + 2, ns, ksg);   // spread: 2 cp.async/ksg
            const int half = ksg >> 1, ks = ksg & 1;
            uint4 av[4];
#pragma unroll
            for (int mf = 0; mf < 4; mf++)
                av[mf] = as[half * 512 + ks * 256 + (wm * 4 + mf) * 32 + lane];
            uint4 bv[2];
#pragma unroll
            for (int np = 0; np < 2; np++)
                bv[np] = bs[half * 512 + (ks * 8 + wn * 2 + np) * 32 + lane];
#pragma unroll
            for (int mf = 0; mf < 4; mf++)
#pragma unroll
                for (int np = 0; np < 2; np++) {
                    mma16816(acc[mf][2 * np],     av[mf], bv[np].x, bv[np].y);
                    mma16816(acc[mf][2 * np + 1], av[mf], bv[np].z, bv[np].w);
                }
        }
        asm volatile("cp.async.commit_group;\n");
        if (++s == STAGES) s = 0;
    }

    // ------------------ epilogue ------------------
    const bool nfull = PACKED_OUT || (n0 + 127 < Nreal);
#pragma unroll
    for (int mf = 0; mf < 4; mf++) {
        const int r0 = m0 + wm * 64 + mf * 16 + lr;
        const int grp = wm * 4 + mf;
#pragma unroll
        for (int npi = 0; npi < 2; npi++) {
            const int nf = npi * 2;
            const int c = n0 + wn * 32 + nf * 8 + lc * 2;
            float b0 = 0.f, b1 = 0.f, b2 = 0.f, b3 = 0.f;
            if (nfull) {
                b0 = __ldg(bias + c);     b1 = __ldg(bias + c + 1);
                b2 = __ldg(bias + c + 8); b3 = __ldg(bias + c + 9);
            } else {
                if (c < Nreal)     b0 = __ldg(bias + c);
                if (c + 1 < Nreal) b1 = __ldg(bias + c + 1);
                if (c + 8 < Nreal) b2 = __ldg(bias + c + 8);
                if (c + 9 < Nreal) b3 = __ldg(bias + c + 9);
            }
            float v00 = acc[mf][nf][0] + b0,     v01 = acc[mf][nf][1] + b1;
            float v10 = acc[mf][nf][2] + b0,     v11 = acc[mf][nf][3] + b1;
            float v20 = acc[mf][nf + 1][0] + b2, v21 = acc[mf][nf + 1][1] + b3;
            float v30 = acc[mf][nf + 1][2] + b2, v31 = acc[mf][nf + 1][3] + b3;
            if (SIGMOID) {
                v00 = 1.f / (1.f + __expf(-v00)); v01 = 1.f / (1.f + __expf(-v01));
                v10 = 1.f / (1.f + __expf(-v10)); v11 = 1.f / (1.f + __expf(-v11));
                v20 = 1.f / (1.f + __expf(-v20)); v21 = 1.f / (1.f + __expf(-v21));
                v30 = 1.f / (1.f + __expf(-v30)); v31 = 1.f / (1.f + __expf(-v31));
            }
            if (PACKED_OUT) {
                int kt2o = c >> 5;
                int ks2 = npi;
                size_t chunk = ((size_t)mt * KTout + kt2o) * 512
                             + ks2 * 256 + grp * 32 + lane;
                uint4 o;
                o.x = pack_half2(v00, v01);
                o.y = pack_half2(v10, v11);
                o.z = pack_half2(v20, v21);
                o.w = pack_half2(v30, v31);
                reinterpret_cast<uint4*>(outp)[chunk] = o;
            } else {
                float* C = reinterpret_cast<float*>(outp);
                if (nfull) {
                    *reinterpret_cast<float2*>(C + (size_t)r0 * Nreal + c) = make_float2(v00, v01);
                    *reinterpret_cast<float2*>(C + (size_t)(r0 + 8) * Nreal + c) = make_float2(v10, v11);
                    *reinterpret_cast<float2*>(C + (size_t)r0 * Nreal + c + 8) = make_float2(v20, v21);
                    *reinterpret_cast<float2*>(C + (size_t)(r0 + 8) * Nreal + c + 8) = make_float2(v30, v31);
                } else {
                    if (c < Nreal)     C[(size_t)r0 * Nreal + c] = v00;
                    if (c + 1 < Nreal) C[(size_t)r0 * Nreal + c + 1] = v01;
                    if (c < Nreal)     C[(size_t)(r0 + 8) * Nreal + c] = v10;
                    if (c + 1 < Nreal) C[(size_t)(r0 + 8) * Nreal + c + 1] = v11;
                    if (c + 8 < Nreal) C[(size_t)r0 * Nreal + c + 8] = v20;
                    if (c + 9 < Nreal) C[(size_t)r0 * Nreal + c + 9] = v21;
                    if (c + 8 < Nreal) C[(size_t)(r0 + 8) * Nreal + c + 8] = v30;
                    if (c + 9 < Nreal) C[(size_t)(r0 + 8) * Nreal + c + 9] = v31;
                }
            }
        }
    }
}

// ---------------------------------------------------------------------------
// Launch
// ---------------------------------------------------------------------------
extern "C" void kernel_launch(void* const* d_in, const int* in_sizes, int n_in,
                              void* d_out, int out_size) {
    const float* x       = (const float*)d_in[0];
    const float* centers = (const float*)d_in[1];
    const float* scales  = (const float*)d_in[2];
    const float* Wb      = (const float*)d_in[3];
    const float* bb      = (const float*)d_in[4];
    const float* Wh      = (const float*)d_in[5];
    const float* bh      = (const float*)d_in[6];
    float* out = (float*)d_out;

    uint4 *F, *PHI, *WbP, *WhP;
    cudaGetSymbolAddress((void**)&F, g_F);
    cudaGetSymbolAddress((void**)&PHI, g_PHI);
    cudaGetSymbolAddress((void**)&WbP, g_WbP);
    cudaGetSymbolAddress((void**)&WhP, g_WhP);

    cudaFuncSetAttribute((const void*)gemm_fp16_kernel<true, true>,
                         cudaFuncAttributeMaxDynamicSharedMemorySize, SMEM_BYTES);
    cudaFuncSetAttribute((const void*)gemm_fp16_kernel<false, false>,
                         cudaFuncAttributeMaxDynamicSharedMemorySize, SMEM_BYTES);

    // 1) fused prep: feats + Wb pack + Wh pack (interleaved blocks)
    prep_fused_kernel<<<PREP_BLOCKS, 256>>>(x, centers, scales, Wb, Wh,
                                            F, WbP, WhP);

    // 2) GEMM1: PHI(packed) = sigmoid(F @ Wb + bb)
    {
        int nT = HIDDEN / 128;
        int grid = (BATCH / 128) * nT;
        gemm_fp16_kernel<true, true><<<grid, 256, SMEM_BYTES>>>(
            F, WbP, bb, PHI, KT1, KT2, HIDDEN, nT);
    }
    // 3) GEMM2: out = PHI @ Wh + bh
    {
        int nT = NPAD / 128;
        int grid = (BATCH / 128) * nT;
        gemm_fp16_kernel<false, false><<<grid, 256, SMEM_BYTES>>>(
            PHI, WhP, bh, out, KT2, 0, CLASSES, nT);
    }
}

// round 17
// speedup vs baseline: 1.0642x; 1.0167x over previous
#include <cuda_runtime.h>
#include <cuda_fp16.h>
#include <cstdint>

// ---------------------------------------------------------------------------
// KANClassifier fp16 mma.sync. Round 17: persistent GEMM kernel (grid =
// 2 x SM count, all CTAs resident) pulling tiles off a global work queue:
// items [0,1024) = GEMM1 tiles, [1024,1280) = GEMM2 tiles (dependency via
// per-mt counters; queue order makes spins always make progress).
// GEMM body = round-16 spread-cp.async mainloop (best, 1395.8us).
// ---------------------------------------------------------------------------

#define BATCH   4096
#define IN_DIM  1024
#define KDIM    16384
#define HIDDEN  4096
#define CLASSES 1000
#define NPAD    1024

#define KT1 (KDIM / 32)               // 512
#define KT2 (HIDDEN / 32)             // 128
#define CONVB_BLOCKS (KT1 * (HIDDEN / 128))   // 16384
#define CONVH_BLOCKS (KT2 * (NPAD / 128))     // 1024
#define PREP_BLOCKS (2 * CONVB_BLOCKS + CONVH_BLOCKS)

#define G1_NT 32
#define G2_NT 8
#define G1_ITEMS 1024
#define G2_ITEMS 256
#define TOTAL_ITEMS (G1_ITEMS + G2_ITEMS)
#define MT_COUNT (BATCH / 128)        // 32

__device__ __align__(1024) uint4 g_F  [(size_t)BATCH * KDIM / 8];
__device__ __align__(1024) uint4 g_PHI[(size_t)BATCH * HIDDEN / 8];
__device__ __align__(1024) uint4 g_WbP[(size_t)KDIM * HIDDEN / 8];
__device__ __align__(1024) uint4 g_WhP[(size_t)HIDDEN * NPAD / 8];
__device__ int g_done[MT_COUNT];
__device__ int g_next;

__device__ __forceinline__ uint32_t pack_half2(float a, float b) {
    __half2 h = __floats2half2_rn(a, b);
    return *reinterpret_cast<uint32_t*>(&h);
}
__device__ __forceinline__ float mufu_tanh(float v) {
    float r;
    asm("tanh.approx.f32 %0, %1;" : "=f"(r) : "f"(v));
    return r;
}
__device__ __forceinline__ void cp_async16(uint32_t saddr, const void* gptr) {
    asm volatile("cp.async.cg.shared.global [%0], [%1], 16;\n" :: "r"(saddr), "l"(gptr));
}

// ---------------------------------------------------------------------------
// Fused prep kernel (round-12 winner) + queue/counter zeroing.
// ---------------------------------------------------------------------------
__device__ __forceinline__ void feats_block(int blk,
                                            const float* __restrict__ x,
                                            const float* __restrict__ centers,
                                            const float* __restrict__ scales,
                                            uint4* __restrict__ F) {
    int cp = blk * 256 + threadIdx.x;
    int g2 = cp * 2;
    int lane = g2 & 31, grp = (g2 >> 5) & 7, ks = (g2 >> 8) & 1;
    int kt = (g2 >> 9) & (KT1 - 1), mt = g2 >> 18;
    int rlo = lane >> 2;
    int j0 = (lane & 3) * 2;
    int r = mt * 128 + grp * 16 + rlo;
    int d = kt * 2 + ks;

    float xv0 = __ldg(x + (size_t)r * IN_DIM + d);
    float xv1 = __ldg(x + (size_t)(r + 8) * IN_DIM + d);
    const float4* c4 = reinterpret_cast<const float4*>(centers + d * 16 + j0);
    const float4* s4 = reinterpret_cast<const float4*>(scales  + d * 16 + j0);
    float4 cA = __ldg(c4);
    float4 cB = __ldg(c4 + 2);
    float4 sA = __ldg(s4);
    float4 sB = __ldg(s4 + 2);

    uint4 o0, o1;
    o0.x = pack_half2(mufu_tanh((xv0 - cA.x) * sA.x), mufu_tanh((xv0 - cA.y) * sA.y));
    o0.y = pack_half2(mufu_tanh((xv1 - cA.x) * sA.x), mufu_tanh((xv1 - cA.y) * sA.y));
    o0.z = pack_half2(mufu_tanh((xv0 - cB.x) * sB.x), mufu_tanh((xv0 - cB.y) * sB.y));
    o0.w = pack_half2(mufu_tanh((xv1 - cB.x) * sB.x), mufu_tanh((xv1 - cB.y) * sB.y));
    o1.x = pack_half2(mufu_tanh((xv0 - cA.z) * sA.z), mufu_tanh((xv0 - cA.w) * sA.w));
    o1.y = pack_half2(mufu_tanh((xv1 - cA.z) * sA.z), mufu_tanh((xv1 - cA.w) * sA.w));
    o1.z = pack_half2(mufu_tanh((xv0 - cB.z) * sB.z), mufu_tanh((xv0 - cB.w) * sB.w));
    o1.w = pack_half2(mufu_tanh((xv1 - cB.z) * sB.z), mufu_tanh((xv1 - cB.w) * sB.w));
    F[g2]     = o0;
    F[g2 + 1] = o1;
}

__device__ __forceinline__ void convert_block(int tile, float (*s)[132],
                                              const float* __restrict__ W,
                                              uint4* __restrict__ out,
                                              int KT, int Nsrc) {
    const int kt = tile % KT, nt = tile / KT;
    const int tid = threadIdx.x;
    const int n0 = nt * 128;

    const float* wg = W + (size_t)(kt * 32) * Nsrc + n0;
#pragma unroll
    for (int p = 0; p < 4; p++) {
        int elem = p * 1024 + tid * 4;
        int row = elem >> 7, col = elem & 127;
        float4 v;
        if (n0 + col + 3 < Nsrc) {
            v = __ldg(reinterpret_cast<const float4*>(wg + (size_t)row * Nsrc + col));
        } else {
            v.x = (n0 + col     < Nsrc) ? __ldg(wg + (size_t)row * Nsrc + col)     : 0.f;
            v.y = (n0 + col + 1 < Nsrc) ? __ldg(wg + (size_t)row * Nsrc + col + 1) : 0.f;
            v.z = (n0 + col + 2 < Nsrc) ? __ldg(wg + (size_t)row * Nsrc + col + 2) : 0.f;
            v.w = (n0 + col + 3 < Nsrc) ? __ldg(wg + (size_t)row * Nsrc + col + 3) : 0.f;
        }
        s[row][col] = v.x; s[row][col + 1] = v.y;
        s[row][col + 2] = v.z; s[row][col + 3] = v.w;
    }
    __syncthreads();

#pragma unroll
    for (int q = 0; q < 2; q++) {
        int cc = tid * 2 + q;
        int lane = cc & 31, npair = (cc >> 5) & 7, ks = cc >> 8;
        int k0 = ks * 16 + (lane & 3) * 2;
        int c  = npair * 16 + (lane >> 2);
        uint4 o;
        o.x = pack_half2(s[k0][c],         s[k0 + 1][c]);
        o.y = pack_half2(s[k0 + 8][c],     s[k0 + 9][c]);
        o.z = pack_half2(s[k0][c + 8],     s[k0 + 1][c + 8]);
        o.w = pack_half2(s[k0 + 8][c + 8], s[k0 + 9][c + 8]);
        out[(size_t)tile * 512 + cc] = o;
    }
}

__global__ void prep_fused_kernel(const float* __restrict__ x,
                                  const float* __restrict__ centers,
                                  const float* __restrict__ scales,
                                  const float* __restrict__ Wb,
                                  const float* __restrict__ Wh,
                                  uint4* __restrict__ F,
                                  uint4* __restrict__ WbP,
                                  uint4* __restrict__ WhP) {
    __shared__ float s[32][132];
    int b = blockIdx.x;
    if (b == 0) {
        if (threadIdx.x < MT_COUNT) g_done[threadIdx.x] = 0;
        if (threadIdx.x == MT_COUNT) g_next = 0;
    }
    if (b < 2 * CONVB_BLOCKS) {
        if (b & 1) feats_block(b >> 1, x, centers, scales, F);
        else       convert_block(b >> 1, s, Wb, WbP, KT1, HIDDEN);
    } else {
        convert_block(b - 2 * CONVB_BLOCKS, s, Wh, WhP, KT2, CLASSES);
    }
}

// ---------------------------------------------------------------------------
// GEMM body (round-16 mainloop): 128x128 block, BK=64, 3 stages (96KB),
// 8 warps (2M x 4N), spread cp.async (2 per ksg).
// ---------------------------------------------------------------------------
#define STAGES 3
#define A_CH 1024
#define B_CH 1024
#define SMEM_BYTES (STAGES * (A_CH + B_CH) * 16)   // 96KB

__device__ __forceinline__ void mma16816(float* d, const uint4& a,
                                         uint32_t b0, uint32_t b1) {
    asm volatile(
        "mma.sync.aligned.m16n8k16.row.col.f32.f16.f16.f32 "
        "{%0,%1,%2,%3}, {%4,%5,%6,%7}, {%8,%9}, {%0,%1,%2,%3};\n"
        : "+f"(d[0]), "+f"(d[1]), "+f"(d[2]), "+f"(d[3])
        : "r"(a.x), "r"(a.y), "r"(a.z), "r"(a.w), "r"(b0), "r"(b1));
}

template <bool SIGMOID, bool PACKED_OUT>
__device__ __forceinline__ void gemm_body(int mt, int nt,
                                          const uint4* __restrict__ Apk,
                                          const uint4* __restrict__ Bpk,
                                          const float* __restrict__ bias,
                                          void* __restrict__ outp,
                                          int KTs, int KTout, int Nreal) {
    extern __shared__ uint4 sm4[];
    uint4* As = sm4;
    uint4* Bs = sm4 + STAGES * A_CH;

    const int tid = threadIdx.x;
    const int lane = tid & 31;
    const int warp = tid >> 5;
    const int wm = warp & 1, wn = warp >> 1;
    const int lr = lane >> 2, lc = lane & 3;
    const int m0 = mt * 128, n0 = nt * 128;
    const int KT2c = KTs / 2;

    float acc[4][4][4];
#pragma unroll
    for (int i = 0; i < 4; i++)
#pragma unroll
        for (int j = 0; j < 4; j++)
#pragma unroll
            for (int k = 0; k < 4; k++) acc[i][j][k] = 0.f;

    auto load_part = [&](int kt2, int s, int p) {
        int ci = tid + p * 256;
        const uint4* ag = Apk + ((size_t)mt * KTs + kt2 * 2) * 512;
        cp_async16((uint32_t)__cvta_generic_to_shared(As + s * A_CH + ci), ag + ci);
        const uint4* bg = Bpk + ((size_t)nt * KTs + kt2 * 2) * 512;
        cp_async16((uint32_t)__cvta_generic_to_shared(Bs + s * B_CH + ci), bg + ci);
    };
    auto load_full = [&](int kt2, int s) {
#pragma unroll
        for (int p = 0; p < 4; p++) load_part(kt2, s, p);
        asm volatile("cp.async.commit_group;\n");
    };

    load_full(0, 0);
    load_full(1, 1);

    int s = 0;
    for (int kt2 = 0; kt2 < KT2c; kt2++) {
        asm volatile("cp.async.wait_group 1;\n");
        __syncthreads();
        const bool pref = (kt2 + 2 < KT2c);
        int ns = s + 2; if (ns >= STAGES) ns -= STAGES;

        const uint4* as = As + s * A_CH;
        const uint4* bs = Bs + s * B_CH;

#pragma unroll
        for (int ksg = 0; ksg < 4; ksg++) {
            if (pref) load_part(kt2 + 2, ns, ksg);
            const int half = ksg >> 1, ks = ksg & 1;
            uint4 av[4];
#pragma unroll
            for (int mf = 0; mf < 4; mf++)
                av[mf] = as[half * 512 + ks * 256 + (wm * 4 + mf) * 32 + lane];
            uint4 bv[2];
#pragma unroll
            for (int np = 0; np < 2; np++)
                bv[np] = bs[half * 512 + (ks * 8 + wn * 2 + np) * 32 + lane];
#pragma unroll
            for (int mf = 0; mf < 4; mf++)
#pragma unroll
                for (int np = 0; np < 2; np++) {
                    mma16816(acc[mf][2 * np],     av[mf], bv[np].x, bv[np].y);
                    mma16816(acc[mf][2 * np + 1], av[mf], bv[np].z, bv[np].w);
                }
        }
        asm volatile("cp.async.commit_group;\n");
        if (++s == STAGES) s = 0;
    }
    // drain outstanding cp.async groups so next tile's stage fills are clean
    asm volatile("cp.async.wait_group 0;\n");

    // ------------------ epilogue ------------------
    const bool nfull = PACKED_OUT || (n0 + 127 < Nreal);
#pragma unroll
    for (int mf = 0; mf < 4; mf++) {
        const int r0 = m0 + wm * 64 + mf * 16 + lr;
        const int grp = wm * 4 + mf;
#pragma unroll
        for (int npi = 0; npi < 2; npi++) {
            const int nf = npi * 2;
            const int c = n0 + wn * 32 + nf * 8 + lc * 2;
            float b0 = 0.f, b1 = 0.f, b2 = 0.f, b3 = 0.f;
            if (nfull) {
                b0 = __ldg(bias + c);     b1 = __ldg(bias + c + 1);
                b2 = __ldg(bias + c + 8); b3 = __ldg(bias + c + 9);
            } else {
                if (c < Nreal)     b0 = __ldg(bias + c);
                if (c + 1 < Nreal) b1 = __ldg(bias + c + 1);
                if (c + 8 < Nreal) b2 = __ldg(bias + c + 8);
                if (c + 9 < Nreal) b3 = __ldg(bias + c + 9);
            }
            float v00 = acc[mf][nf][0] + b0,     v01 = acc[mf][nf][1] + b1;
            float v10 = acc[mf][nf][2] + b0,     v11 = acc[mf][nf][3] + b1;
            float v20 = acc[mf][nf + 1][0] + b2, v21 = acc[mf][nf + 1][1] + b3;
            float v30 = acc[mf][nf + 1][2] + b2, v31 = acc[mf][nf + 1][3] + b3;
            if (SIGMOID) {
                v00 = 1.f / (1.f + __expf(-v00)); v01 = 1.f / (1.f + __expf(-v01));
                v10 = 1.f / (1.f + __expf(-v10)); v11 = 1.f / (1.f + __expf(-v11));
                v20 = 1.f / (1.f + __expf(-v20)); v21 = 1.f / (1.f + __expf(-v21));
                v30 = 1.f / (1.f + __expf(-v30)); v31 = 1.f / (1.f + __expf(-v31));
            }
            if (PACKED_OUT) {
                int kt2o = c >> 5;
                int ks2 = npi;
                size_t chunk = ((size_t)mt * KTout + kt2o) * 512
                             + ks2 * 256 + grp * 32 + lane;
                uint4 o;
                o.x = pack_half2(v00, v01);
                o.y = pack_half2(v10, v11);
                o.z = pack_half2(v20, v21);
                o.w = pack_half2(v30, v31);
                reinterpret_cast<uint4*>(outp)[chunk] = o;
            } else {
                float* C = reinterpret_cast<float*>(outp);
                if (nfull) {
                    *reinterpret_cast<float2*>(C + (size_t)r0 * Nreal + c) = make_float2(v00, v01);
                    *reinterpret_cast<float2*>(C + (size_t)(r0 + 8) * Nreal + c) = make_float2(v10, v11);
                    *reinterpret_cast<float2*>(C + (size_t)r0 * Nreal + c + 8) = make_float2(v20, v21);
                    *reinterpret_cast<float2*>(C + (size_t)(r0 + 8) * Nreal + c + 8) = make_float2(v30, v31);
                } else {
                    if (c < Nreal)     C[(size_t)r0 * Nreal + c] = v00;
                    if (c + 1 < Nreal) C[(size_t)r0 * Nreal + c + 1] = v01;
                    if (c < Nreal)     C[(size_t)(r0 + 8) * Nreal + c] = v10;
                    if (c + 1 < Nreal) C[(size_t)(r0 + 8) * Nreal + c + 1] = v11;
                    if (c + 8 < Nreal) C[(size_t)r0 * Nreal + c + 8] = v20;
                    if (c + 9 < Nreal) C[(size_t)r0 * Nreal + c + 9] = v21;
                    if (c + 8 < Nreal) C[(size_t)(r0 + 8) * Nreal + c + 8] = v30;
                    if (c + 9 < Nreal) C[(size_t)(r0 + 8) * Nreal + c + 9] = v31;
                }
            }
        }
    }
}

// ---------------------------------------------------------------------------
// Persistent GEMM kernel: all CTAs resident; items pulled off g_next.
// ---------------------------------------------------------------------------
__global__ void __launch_bounds__(256, 2)
gemm_persistent_kernel(const uint4* __restrict__ F,
                       const uint4* __restrict__ WbP,
                       const float* __restrict__ bb,
                       uint4* __restrict__ PHI,
                       const uint4* __restrict__ WhP,
                       const float* __restrict__ bh,
                       float* __restrict__ out) {
    __shared__ int s_item;
    const int GRP = 8;
    for (;;) {
        if (threadIdx.x == 0) s_item = atomicAdd(&g_next, 1);
        __syncthreads();   // also orders prev tile's smem reads before refill
        int item = s_item;
        if (item >= TOTAL_ITEMS) return;

        if (item < G1_ITEMS) {
            int per = GRP * G1_NT;   // 256
            int mt = (item / per) * GRP + (item % per) % GRP;
            int nt = (item % per) / GRP;
            gemm_body<true, true>(mt, nt, F, WbP, bb, PHI, KT1, KT2, HIDDEN);
            __syncthreads();
            if (threadIdx.x == 0) {
                __threadfence();
                atomicAdd(&g_done[mt], 1);
            }
        } else {
            int cid = item - G1_ITEMS;
            int per = GRP * G2_NT;   // 64
            int mt = (cid / per) * GRP + (cid % per) % GRP;
            int nt = (cid % per) / GRP;
            if (threadIdx.x == 0) {
                while (__ldcg((const int*)&g_done[mt]) < G1_NT) __nanosleep(100);
            }
            __syncthreads();
            __threadfence();
            gemm_body<false, false>(mt, nt, PHI, WhP, bh, out, KT2, 0, CLASSES);
        }
    }
}

// ---------------------------------------------------------------------------
// Launch
// ---------------------------------------------------------------------------
extern "C" void kernel_launch(void* const* d_in, const int* in_sizes, int n_in,
                              void* d_out, int out_size) {
    const float* x       = (const float*)d_in[0];
    const float* centers = (const float*)d_in[1];
    const float* scales  = (const float*)d_in[2];
    const float* Wb      = (const float*)d_in[3];
    const float* bb      = (const float*)d_in[4];
    const float* Wh      = (const float*)d_in[5];
    const float* bh      = (const float*)d_in[6];
    float* out = (float*)d_out;

    uint4 *F, *PHI, *WbP, *WhP;
    cudaGetSymbolAddress((void**)&F, g_F);
    cudaGetSymbolAddress((void**)&PHI, g_PHI);
    cudaGetSymbolAddress((void**)&WbP, g_WbP);
    cudaGetSymbolAddress((void**)&WhP, g_WhP);

    int nsm = 148;
    cudaDeviceGetAttribute(&nsm, cudaDevAttrMultiProcessorCount, 0);

    cudaFuncSetAttribute((const void*)gemm_persistent_kernel,
                         cudaFuncAttributeMaxDynamicSharedMemorySize, SMEM_BYTES);

    // 1) fused prep: feats + Wb pack + Wh pack + queue/counter zeroing
    prep_fused_kernel<<<PREP_BLOCKS, 256>>>(x, centers, scales, Wb, Wh,
                                            F, WbP, WhP);

    // 2) persistent GEMM1+GEMM2
    gemm_persistent_kernel<<<2 * nsm, 256, SMEM_BYTES>>>(
        F, WbP, bb, PHI, WhP, bh, out);
}